// round 17
// baseline (speedup 1.0000x reference)
#include <cuda_runtime.h>
#include <cuda_fp16.h>

#define BB 8
#define NN 2048
#define DD 1024
#define TT 2     // Taylor terms (powers 0..1); weights 1+z, z >= -0.17 > -1
#define CC 64    // chunks along N
#define LL 32    // NN / CC
#define NCTA (BB * CC)   // 512 CTAs, all co-resident (4/SM required for barrier)
#define NTHR 256
#define NCHAINS (BB * TT * DD)          // 16384 vector chains
#define CBLK (NCHAINS / NTHR)           // 64 CTAs do the vector scan
#define SFROWS 27                        // f rows cached in shared as fp16
#define SMEM_DYN (SFROWS * NTHR * 8)     // 55296 bytes (2 half2 per thread per row)

// Scratch (static device arrays; no cudaMalloc allowed)
__device__ __half g_parth[(size_t)BB * CC * TT * DD]; // fp16 chunk moments -> prefixes
__device__ float  g_smom [BB * CC * TT];              // chunk scalar moments (fp32)
__device__ float  g_spref[BB * CC * TT];              // exclusive scalar prefixes
__device__ unsigned int g_barcnt[2];                  // monotonic grid barriers

// Monotonic grid barrier: counter only grows; each launch adds exactly NCTA,
// so target = round_down(old, NCTA) + NCTA is correct across graph replays.
__device__ __forceinline__ void grid_bar(int which) {
    __syncthreads();
    if (threadIdx.x == 0) {
        __threadfence();                                  // publish our writes
        unsigned old = atomicAdd(&g_barcnt[which], 1u);
        unsigned target = (old & ~(unsigned)(NCTA - 1)) + NCTA;
        while ((int)(*(volatile unsigned*)&g_barcnt[which] - target) < 0) {}
        __threadfence();                                  // order spin before reads
    }
    __syncthreads();
}

__global__ __launch_bounds__(NTHR, 4) void k_all(const float* __restrict__ x,
                                                 const float* __restrict__ f,
                                                 const float* __restrict__ wk,
                                                 const float* __restrict__ wq,
                                                 float* __restrict__ out) {
    const int ch   = blockIdx.x;
    const int b    = blockIdx.y;
    const int tid  = threadIdx.x;
    const int wid  = tid >> 5;
    const int lane = tid & 31;
    const int cta  = b * CC + ch;

    __shared__ float sk[LL], sq[LL];
    extern __shared__ __half2 sf[];              // 55296 B: fp16 f-row cache

    // ---- Phase A: k,q projections for this CTA's 32 rows (8 warps x 4) ----
    const float4* wk4 = reinterpret_cast<const float4*>(wk);
    const float4* wq4 = reinterpret_cast<const float4*>(wq);
#pragma unroll
    for (int r = 0; r < 4; r++) {
        int rowl = wid * 4 + r;
        const float4* xr = reinterpret_cast<const float4*>(x) +
                           (size_t)(b * NN + ch * LL + rowl) * (DD / 4);
        float dk = 0.f, dq = 0.f;
#pragma unroll
        for (int i = 0; i < 8; i++) {
            float4 v  = __ldcs(&xr[lane + 32 * i]);   // x never re-read
            float4 a  = wk4[lane + 32 * i];
            float4 bq = wq4[lane + 32 * i];
            dk += v.x * a.x + v.y * a.y + v.z * a.z + v.w * a.w;
            dq += v.x * bq.x + v.y * bq.y + v.z * bq.z + v.w * bq.w;
        }
#pragma unroll
        for (int off = 16; off > 0; off >>= 1) {
            dk += __shfl_down_sync(0xffffffffu, dk, off);
            dq += __shfl_down_sync(0xffffffffu, dq, off);
        }
        if (lane == 0) { sk[rowl] = dk; sq[rowl] = dq; }
    }
    __syncthreads();

    // ---- Phase B: chunk vector moments (float4/thread); cache rows in smem ----
    const float4* fp = reinterpret_cast<const float4*>(
        f + (size_t)(b * NN + ch * LL) * DD) + tid;

    {
        float4 S[TT];
#pragma unroll
        for (int t = 0; t < TT; t++) S[t] = make_float4(0.f, 0.f, 0.f, 0.f);
#pragma unroll 8
        for (int j = 0; j < LL; j++) {
            float4 fv = fp[(size_t)j * (DD / 4)];
            if (j < SFROWS) {                        // cache for phase D (fp16)
                __half2* sfr = sf + ((size_t)j * NTHR + tid) * 2;
                sfr[0] = __floats2half2_rn(fv.x, fv.y);
                sfr[1] = __floats2half2_rn(fv.z, fv.w);
            }
            float kj = sk[j];
            S[0].x += fv.x;      S[0].y += fv.y;      S[0].z += fv.z;      S[0].w += fv.w;
            S[1].x += kj * fv.x; S[1].y += kj * fv.y; S[1].z += kj * fv.z; S[1].w += kj * fv.w;
        }
        __half2* gp = reinterpret_cast<__half2*>(g_parth) +
                      (size_t)(cta * TT) * (DD / 2) + tid * 2;
#pragma unroll
        for (int t = 0; t < TT; t++) {
            gp[(size_t)t * (DD / 2)]     = __floats2half2_rn(S[t].x, S[t].y);
            gp[(size_t)t * (DD / 2) + 1] = __floats2half2_rn(S[t].z, S[t].w);
        }
    }

    if (wid == 0) {   // scalar chunk moment: warp-reduce k over 32 rows (fp32)
        float p1 = sk[lane];
#pragma unroll
        for (int off = 16; off > 0; off >>= 1)
            p1 += __shfl_down_sync(0xffffffffu, p1, off);
        if (lane == 0) {
            g_smom[cta * TT + 0] = (float)LL;
            g_smom[cta * TT + 1] = p1;
        }
    }

    grid_bar(0);

    // ---- Phase C: cross-chunk exclusive scans (fp32 accumulate, fp16 store) ----
    if (cta < CBLK) {
        // vector chains: one per thread, idx in [0, NCHAINS)
        int idx = cta * NTHR + tid;
        int d   = idx % DD;
        int t   = (idx / DD) % TT;
        int bb  = idx / (DD * TT);
        size_t base   = (size_t)((bb * CC) * TT + t) * DD + d;
        size_t stride = (size_t)TT * DD;
        float run = 0.f;
#pragma unroll
        for (int half = 0; half < 2; half++) {
            float v[CC / 2];
#pragma unroll
            for (int c = 0; c < CC / 2; c++)
                v[c] = __half2float(g_parth[base + (half * (CC / 2) + c) * stride]);
#pragma unroll
            for (int c = 0; c < CC / 2; c++) {
                float tmp = v[c];
                v[c] = run;
                run += tmp;
            }
#pragma unroll
            for (int c = 0; c < CC / 2; c++)
                g_parth[base + (half * (CC / 2) + c) * stride] = __float2half_rn(v[c]);
        }
    } else if (cta == CBLK && tid < BB * TT) {
        // scalar chains: (b, t), 64 chunks each, register-blocked (fp32)
        int bb = tid / TT, t = tid % TT;
        float run = 0.f;
#pragma unroll
        for (int half = 0; half < 2; half++) {
            float v[CC / 2];
#pragma unroll
            for (int c = 0; c < CC / 2; c++)
                v[c] = __ldcg(&g_smom[(bb * CC + half * (CC / 2) + c) * TT + t]);
#pragma unroll
            for (int c = 0; c < CC / 2; c++) {
                float tmp = v[c];
                g_spref[(bb * CC + half * (CC / 2) + c) * TT + t] = run;
                run += tmp;
            }
        }
    }

    grid_bar(1);

    // ---- Phase D: resume scan within chunk, inline coefficients, output ----
    float4 S[TT];
    {
        const __half2* gp = reinterpret_cast<const __half2*>(g_parth) +
                            (size_t)(cta * TT) * (DD / 2) + tid * 2;
#pragma unroll
        for (int t = 0; t < TT; t++) {
            float2 lo = __half22float2(__ldcg(&gp[(size_t)t * (DD / 2)]));
            float2 hi = __half22float2(__ldcg(&gp[(size_t)t * (DD / 2) + 1]));
            S[t] = make_float4(lo.x, lo.y, hi.x, hi.y);
        }
    }

    float P0 = __ldcg(&g_spref[cta * TT + 0]);
    float P1 = __ldcg(&g_spref[cta * TT + 1]);

    float4* op = reinterpret_cast<float4*>(
        out + (size_t)(b * NN + ch * LL) * DD) + tid;

#pragma unroll 4
    for (int j = 0; j < LL; j++) {
        float4 fv;
        if (j < SFROWS) {                           // smem hit (fp16 cached in B)
            const __half2* sfr = sf + ((size_t)j * NTHR + tid) * 2;
            float2 lo = __half22float2(sfr[0]);
            float2 hi = __half22float2(sfr[1]);
            fv = make_float4(lo.x, lo.y, hi.x, hi.y);
        } else {
            fv = fp[(size_t)j * (DD / 4)];          // residual rows: L2 hit
        }
        float kj = sk[j];
        S[0].x += fv.x;      S[0].y += fv.y;      S[0].z += fv.z;      S[0].w += fv.w;
        S[1].x += kj * fv.x; S[1].y += kj * fv.y; S[1].z += kj * fv.z; S[1].w += kj * fv.w;
        P0 += 1.f; P1 += kj;

        float co1 = sq[j] * 0.03125f;               // q_j / sqrt(D)
        float Z  = P0 + co1 * P1;
        float iz = 1.f / Z;

        float4 acc;
        acc.x = (S[0].x + co1 * S[1].x) * iz;
        acc.y = (S[0].y + co1 * S[1].y) * iz;
        acc.z = (S[0].z + co1 * S[1].z) * iz;
        acc.w = (S[0].w + co1 * S[1].w) * iz;
        __stcs(&op[(size_t)j * (DD / 4)], acc);     // streaming: never re-read
    }
}

// ---------------------------------------------------------------------------
extern "C" void kernel_launch(void* const* d_in, const int* in_sizes, int n_in,
                              void* d_out, int out_size) {
    const float* x  = (const float*)d_in[0];
    const float* f  = (const float*)d_in[1];
    const float* wk = (const float*)d_in[2];
    const float* wq = (const float*)d_in[3];
    float* out = (float*)d_out;

    // Idempotent host-side attribute (not a stream op; graph-capture safe).
    static int attr_done = 0;
    if (!attr_done) {
        cudaFuncSetAttribute(k_all, cudaFuncAttributeMaxDynamicSharedMemorySize,
                             SMEM_DYN);
        attr_done = 1;
    }

    dim3 g(CC, BB);                          // 512 CTAs x 256 thr — one wave
    k_all<<<g, NTHR, SMEM_DYN>>>(x, f, wk, wq, out);
}